// round 1
// baseline (speedup 1.0000x reference)
#include <cuda_runtime.h>

#define NP 8192        // number of data points
#define NG 128         // grid resolution per axis
#define KSPLIT 64      // K-dimension split factor
#define KSLICE (NP / KSPLIT)   // 128
#define CHUNK 32       // smem K chunk
#define TM 64
#define TN 64

// Static device scratch (allocation-free per harness rules)
__device__ float g_A [NG * NP];   // Ex[xi][k]  = exp(-0.5*(gx[xi]-X[k].x)^2)
__device__ float g_B0[NG * NP];   // Ey[yi][k]  = exp(-0.5*(gy[yi]-X[k].y)^2)
__device__ float g_B1[NG * NP];   // Ey * Y[k].x
__device__ float g_B2[NG * NP];   // Ey * Y[k].y
__device__ float g_part[KSPLIT * 3 * NG * NG];  // K-split partial sums

// ---------------------------------------------------------------------------
// Kernel 1: build the separable RBF tables. 128*8192 = 1M threads, 2 exps each.
// ---------------------------------------------------------------------------
__global__ void __launch_bounds__(256) precompute_kernel(
    const float* __restrict__ X, const float* __restrict__ Y) {
    int idx = blockIdx.x * blockDim.x + threadIdx.x;  // 0 .. NG*NP-1
    int k = idx & (NP - 1);
    int r = idx >> 13;                                // row 0..127
    // linspace(-2, 2, 128): g = -2 + 4*r/127 (x and y axes identical)
    float g = -2.0f + 4.0f * (float)r * (1.0f / 127.0f);
    float xx = X[2 * k];
    float xy = X[2 * k + 1];
    float dx = g - xx;
    float dy = g - xy;
    float ex = __expf(-0.5f * dx * dx);
    float ey = __expf(-0.5f * dy * dy);
    float y0 = Y[2 * k];
    float y1 = Y[2 * k + 1];
    g_A [idx] = ex;
    g_B0[idx] = ey;
    g_B1[idx] = ey * y0;
    g_B2[idx] = ey * y1;
}

// ---------------------------------------------------------------------------
// Kernel 2: fused triple GEMM S_c = Ex @ B_c^T over a K slice.
// 256 blocks = 4 spatial 64x64 tiles x 64 K-slices. 256 threads/block.
// Each thread owns a strided 4x4 micro-tile with 3 channel accumulators.
// ---------------------------------------------------------------------------
__global__ void __launch_bounds__(256) main_kernel() {
    // +1 pad: conflict-free transposed store AND conflict-free strided read
    __shared__ float As [CHUNK][TM + 1];
    __shared__ float Bs0[CHUNK][TN + 1];
    __shared__ float Bs1[CHUNK][TN + 1];
    __shared__ float Bs2[CHUNK][TN + 1];

    int b = blockIdx.x;
    int ks    = b >> 2;              // 0..63 K slice
    int tileM = (b & 1) * TM;        // xi tile
    int tileN = ((b >> 1) & 1) * TN; // yi tile
    int tid = threadIdx.x;
    int tm = tid & 15;
    int tn = tid >> 4;

    float acc0[4][4] = {};
    float acc1[4][4] = {};
    float acc2[4][4] = {};

    int kbase = ks * KSLICE;
    for (int cc = 0; cc < KSLICE; cc += CHUNK) {
        int k0 = kbase + cc;
        // Fill smem: 64 rows x 32 k per table; coalesced global reads along k,
        // transposed conflict-free smem store (pad 65: bank = (kk+m)%32).
        #pragma unroll
        for (int j = 0; j < 8; j++) {
            int flat = j * 256 + tid;   // 0..2047
            int m  = flat >> 5;
            int kk = flat & 31;
            As [kk][m] = g_A [(tileM + m) * NP + k0 + kk];
            Bs0[kk][m] = g_B0[(tileN + m) * NP + k0 + kk];
            Bs1[kk][m] = g_B1[(tileN + m) * NP + k0 + kk];
            Bs2[kk][m] = g_B2[(tileN + m) * NP + k0 + kk];
        }
        __syncthreads();

        #pragma unroll 4
        for (int k = 0; k < CHUNK; k++) {
            float a[4], b0[4], b1[4], b2[4];
            #pragma unroll
            for (int r = 0; r < 4; r++) a[r] = As[k][tm + 16 * r];
            #pragma unroll
            for (int c = 0; c < 4; c++) {
                b0[c] = Bs0[k][tn + 16 * c];
                b1[c] = Bs1[k][tn + 16 * c];
                b2[c] = Bs2[k][tn + 16 * c];
            }
            #pragma unroll
            for (int r = 0; r < 4; r++) {
                #pragma unroll
                for (int c = 0; c < 4; c++) {
                    acc0[r][c] += a[r] * b0[c];
                    acc1[r][c] += a[r] * b1[c];
                    acc2[r][c] += a[r] * b2[c];
                }
            }
        }
        __syncthreads();
    }

    // Partials stored already in output spatial order: idx = yi*128 + xi
    float* p0 = g_part + (ks * 3 + 0) * (NG * NG);
    float* p1 = g_part + (ks * 3 + 1) * (NG * NG);
    float* p2 = g_part + (ks * 3 + 2) * (NG * NG);
    #pragma unroll
    for (int r = 0; r < 4; r++) {
        #pragma unroll
        for (int c = 0; c < 4; c++) {
            int m = tileM + tm + 16 * r;   // xi
            int n = tileN + tn + 16 * c;   // yi
            int o = n * NG + m;
            p0[o] = acc0[r][c];
            p1[o] = acc1[r][c];
            p2[o] = acc2[r][c];
        }
    }
}

// ---------------------------------------------------------------------------
// Kernel 3: reduce K-split partials, normalize channels 1,2 by channel 0.
// out[c*16384 + yi*128 + xi]
// ---------------------------------------------------------------------------
__global__ void __launch_bounds__(256) reduce_kernel(float* __restrict__ out) {
    int g = blockIdx.x * blockDim.x + threadIdx.x;  // 0..16383
    float s0 = 0.0f, s1 = 0.0f, s2 = 0.0f;
    #pragma unroll 8
    for (int ks = 0; ks < KSPLIT; ks++) {
        s0 += g_part[(ks * 3 + 0) * (NG * NG) + g];
        s1 += g_part[(ks * 3 + 1) * (NG * NG) + g];
        s2 += g_part[(ks * 3 + 2) * (NG * NG) + g];
    }
    float inv = 1.0f / s0;
    out[g]                = s0;
    out[NG * NG + g]      = s1 * inv;
    out[2 * NG * NG + g]  = s2 * inv;
}

extern "C" void kernel_launch(void* const* d_in, const int* in_sizes, int n_in,
                              void* d_out, int out_size) {
    const float* X = (const float*)d_in[0];
    const float* Y = (const float*)d_in[1];
    float* out = (float*)d_out;

    precompute_kernel<<<(NG * NP) / 256, 256>>>(X, Y);
    main_kernel<<<KSPLIT * 4, 256>>>();
    reduce_kernel<<<(NG * NG) / 256, 256>>>(out);
}

// round 2
// speedup vs baseline: 1.2455x; 1.2455x over previous
#include <cuda_runtime.h>

#define NP 8192
#define NG 128
#define KSPLIT 74          // K slices (2*74 = 148 blocks = one full wave)
#define CHUNK 32
#define NTHREADS 512

typedef unsigned long long u64;

// K-split partial sums: [ks][ch][y*128+x]
__device__ float g_part[KSPLIT * 3 * NG * NG];

#define PACK2(d, s)  asm("mov.b64 %0, {%1, %1};" : "=l"(d) : "r"(__float_as_uint(s)))
#define FMA2(d, a, b) asm("fma.rn.f32x2 %0, %1, %2, %0;" : "+l"(d) : "l"(a), "l"(b))
#define UNPACK2(lo, hi, s) asm("mov.b64 {%0, %1}, %2;" : "=r"(lo), "=r"(hi) : "l"(s))

// ---------------------------------------------------------------------------
// Fused kernel: builds separable RBF tables in smem on the fly, then runs the
// triple GEMM S_c[x][y] = sum_k Ex[x][k] * B_c[y][k] over one K slice with
// packed f32x2 FMAs. Grid: 148 blocks = 2 (N tiles of 64) x 74 (K slices).
// ---------------------------------------------------------------------------
__global__ void __launch_bounds__(NTHREADS, 1) main_kernel(
    const float* __restrict__ X, const float* __restrict__ Y) {

    __shared__ float As[CHUNK][NG + 1];                  // Ex, [k][m], m = x idx
    __shared__ __align__(16) float Bs0[CHUNK][68];       // Ey
    __shared__ __align__(16) float Bs1[CHUNK][68];       // Ey * Y0
    __shared__ __align__(16) float Bs2[CHUNK][68];       // Ey * Y1

    const float GSTEP = 4.0f / 127.0f;
    int b = blockIdx.x;
    int ks    = b >> 1;
    int tileN = (b & 1) * 64;
    int tid = threadIdx.x;
    int tm = tid & 31;     // m-group: m = tm + 32r
    int tn = tid >> 5;     // n-group: n = 4*tn + c  (0..15)

    const float2* Xv = (const float2*)X;
    const float2* Yv = (const float2*)Y;

    u64 acc[3][4][2];      // [ch][r][npair], each holds 2 packed fp32
    #pragma unroll
    for (int c = 0; c < 3; c++)
        #pragma unroll
        for (int r = 0; r < 4; r++) { acc[c][r][0] = 0ull; acc[c][r][1] = 0ull; }

    int kbeg = (ks * NP) / KSPLIT;
    int kend = ((ks + 1) * NP) / KSPLIT;

    for (int cc = kbeg; cc < kend; cc += CHUNK) {
        int rem = kend - cc;   // may be < CHUNK on last chunk -> zero pad

        // ---- Fill A: 128 m x 32 k values, 8 per thread -------------------
        #pragma unroll
        for (int j = 0; j < 8; j++) {
            int v = j * NTHREADS + tid;
            int m = v & 127, kk = v >> 7;
            float ex = 0.0f;
            if (kk < rem) {
                float2 xv = Xv[cc + kk];
                float dx = fmaf((float)m, GSTEP, -2.0f) - xv.x;
                ex = __expf(-0.5f * dx * dx);
            }
            As[kk][m] = ex;
        }
        // ---- Fill B tables: 64 n x 32 k values, 4 per thread -------------
        #pragma unroll
        for (int j = 0; j < 4; j++) {
            int v = j * NTHREADS + tid;
            int n = v & 63, kk = v >> 6;
            float ey = 0.0f, y0 = 0.0f, y1 = 0.0f;
            if (kk < rem) {
                float2 xv = Xv[cc + kk];
                float2 yv = Yv[cc + kk];
                float dy = fmaf((float)(tileN + n), GSTEP, -2.0f) - xv.y;
                ey = __expf(-0.5f * dy * dy);
                y0 = yv.x; y1 = yv.y;
            }
            Bs0[kk][n] = ey;
            Bs1[kk][n] = ey * y0;
            Bs2[kk][n] = ey * y1;
        }
        __syncthreads();

        // ---- MMA over the chunk (zero-padded tail contributes 0) ---------
        #pragma unroll 8
        for (int k = 0; k < CHUNK; k++) {
            u64 a2[4];
            #pragma unroll
            for (int r = 0; r < 4; r++) {
                float a = As[k][tm + 32 * r];
                PACK2(a2[r], a);
            }
            // whole warp reads the same address -> smem broadcast
            ulonglong2 b0 = *reinterpret_cast<const ulonglong2*>(&Bs0[k][4 * tn]);
            ulonglong2 b1 = *reinterpret_cast<const ulonglong2*>(&Bs1[k][4 * tn]);
            ulonglong2 b2 = *reinterpret_cast<const ulonglong2*>(&Bs2[k][4 * tn]);
            #pragma unroll
            for (int r = 0; r < 4; r++) {
                FMA2(acc[0][r][0], a2[r], b0.x);
                FMA2(acc[0][r][1], a2[r], b0.y);
                FMA2(acc[1][r][0], a2[r], b1.x);
                FMA2(acc[1][r][1], a2[r], b1.y);
                FMA2(acc[2][r][0], a2[r], b2.x);
                FMA2(acc[2][r][1], a2[r], b2.y);
            }
        }
        __syncthreads();
    }

    // ---- Write partials: [ks][ch][n*128 + m], coalesced along m ----------
    float* base = g_part + ks * 3 * (NG * NG);
    #pragma unroll
    for (int c = 0; c < 3; c++) {
        #pragma unroll
        for (int r = 0; r < 4; r++) {
            #pragma unroll
            for (int p = 0; p < 2; p++) {
                unsigned lo, hi;
                UNPACK2(lo, hi, acc[c][r][p]);
                int m = tm + 32 * r;
                int n = tileN + 4 * tn + 2 * p;
                base[c * (NG * NG) + n * NG + m]       = __uint_as_float(lo);
                base[c * (NG * NG) + (n + 1) * NG + m] = __uint_as_float(hi);
            }
        }
    }
}

// ---------------------------------------------------------------------------
// Reduce: sum 74 K-slice partials per output element, normalize ch1/ch2 by
// ch0. 128 blocks (one per y row), 256 threads (2 half-sums of 37 slices).
// ---------------------------------------------------------------------------
__global__ void __launch_bounds__(256) reduce_kernel(float* __restrict__ out) {
    __shared__ float sp[3][2][128];
    int t = threadIdx.x, b = blockIdx.x;
    int gg = t & 127, half = t >> 7;
    int gbase = b * NG + gg;

    float s0 = 0.0f, s1 = 0.0f, s2 = 0.0f;
    int ks0 = half * 37;
    #pragma unroll 4
    for (int i = 0; i < 37; i++) {
        const float* p = g_part + (ks0 + i) * 3 * (NG * NG) + gbase;
        s0 += p[0];
        s1 += p[NG * NG];
        s2 += p[2 * NG * NG];
    }
    sp[0][half][gg] = s0;
    sp[1][half][gg] = s1;
    sp[2][half][gg] = s2;
    __syncthreads();

    if (t < 128) {
        float t0 = sp[0][0][t] + sp[0][1][t];
        float t1 = sp[1][0][t] + sp[1][1][t];
        float t2 = sp[2][0][t] + sp[2][1][t];
        float inv = 1.0f / t0;
        out[b * NG + t]                 = t0;
        out[NG * NG + b * NG + t]       = t1 * inv;
        out[2 * NG * NG + b * NG + t]   = t2 * inv;
    }
}

extern "C" void kernel_launch(void* const* d_in, const int* in_sizes, int n_in,
                              void* d_out, int out_size) {
    const float* X = (const float*)d_in[0];
    const float* Y = (const float*)d_in[1];
    float* out = (float*)d_out;

    main_kernel<<<2 * KSPLIT, NTHREADS>>>(X, Y);
    reduce_kernel<<<NG, 256>>>(out);
}

// round 3
// speedup vs baseline: 1.3252x; 1.0640x over previous
#include <cuda_runtime.h>

#define NP 8192
#define NG 128
#define NGNG (NG * NG)
#define KSPLIT 74          // K slices (2*74 = 148 blocks = one full wave)
#define CHUNK 16
#define NTHREADS 512
#define NSPLIT2 8          // second-stage reduce splits

typedef unsigned long long u64;

// K-split partial sums: [ks][ch][y*128+x]
__device__ float g_part[KSPLIT * 3 * NGNG];
// Stage-1 reduce output: [ch][split][g]
__device__ float g_p2[3 * NSPLIT2 * NGNG];

#define PACK2(d, s)  asm("mov.b64 %0, {%1, %1};" : "=l"(d) : "r"(__float_as_uint(s)))
#define FMA2(d, a, b) asm("fma.rn.f32x2 %0, %1, %2, %0;" : "+l"(d) : "l"(a), "l"(b))
#define UNPACK2(lo, hi, s) asm("mov.b64 {%0, %1}, %2;" : "=r"(lo), "=r"(hi) : "l"(s))

// ---------------------------------------------------------------------------
// Fused kernel: builds separable RBF tables into double-buffered smem while
// the FMA pipe chews on the previous chunk. Triple GEMM
// S_c[x][y] = sum_k Ex[x][k] * B_c[y][k], packed f32x2 FMAs.
// Grid: 148 blocks = 2 (N tiles of 64) x 74 (K slices) = one full wave.
// ---------------------------------------------------------------------------
__global__ void __launch_bounds__(NTHREADS, 1) main_kernel(
    const float* __restrict__ X, const float* __restrict__ Y) {

    __shared__ float As[2][CHUNK][NG + 1];               // Ex  [k][m]
    __shared__ __align__(16) float Bs[2][3][CHUNK][68];  // Ey, Ey*Y0, Ey*Y1

    const float GSTEP = 4.0f / 127.0f;
    int b = blockIdx.x;
    int ks    = b >> 1;
    int tileN = (b & 1) * 64;
    int tid = threadIdx.x;
    int tm = tid & 31;     // m = tm + 32r
    int tn = tid >> 5;     // n = 4*tn + c

    const float2* Xv = (const float2*)X;
    const float2* Yv = (const float2*)Y;

    u64 acc[3][4][2];
    #pragma unroll
    for (int c = 0; c < 3; c++)
        #pragma unroll
        for (int r = 0; r < 4; r++) { acc[c][r][0] = 0ull; acc[c][r][1] = 0ull; }

    int kbeg = (ks * NP) / KSPLIT;
    int kend = ((ks + 1) * NP) / KSPLIT;
    int nch = (kend - kbeg + CHUNK - 1) / CHUNK;

    auto fill = [&](int buf, int k0) {
        int rem = kend - k0;
        // A: 128 m x 16 k, 4 per thread
        #pragma unroll
        for (int j = 0; j < 4; j++) {
            int v = j * NTHREADS + tid;
            int m = v & 127, kk = v >> 7;
            float ex = 0.0f;
            if (kk < rem) {
                float2 xv = Xv[k0 + kk];
                float dx = fmaf((float)m, GSTEP, -2.0f) - xv.x;
                ex = __expf(-0.5f * dx * dx);
            }
            As[buf][kk][m] = ex;
        }
        // B: 64 n x 16 k, 2 per thread
        #pragma unroll
        for (int j = 0; j < 2; j++) {
            int v = j * NTHREADS + tid;
            int n = v & 63, kk = v >> 6;
            float ey = 0.0f, y0 = 0.0f, y1 = 0.0f;
            if (kk < rem) {
                float2 xv = Xv[k0 + kk];
                float2 yv = Yv[k0 + kk];
                float dy = fmaf((float)(tileN + n), GSTEP, -2.0f) - xv.y;
                ey = __expf(-0.5f * dy * dy);
                y0 = yv.x; y1 = yv.y;
            }
            Bs[buf][0][kk][n] = ey;
            Bs[buf][1][kk][n] = ey * y0;
            Bs[buf][2][kk][n] = ey * y1;
        }
    };

    fill(0, kbeg);
    __syncthreads();

    for (int c = 0; c < nch; c++) {
        int buf = c & 1;
        if (c + 1 < nch) fill(buf ^ 1, kbeg + (c + 1) * CHUNK);

        #pragma unroll
        for (int k = 0; k < CHUNK; k++) {
            u64 a2[4];
            #pragma unroll
            for (int r = 0; r < 4; r++) {
                float a = As[buf][k][tm + 32 * r];
                PACK2(a2[r], a);
            }
            ulonglong2 b0 = *reinterpret_cast<const ulonglong2*>(&Bs[buf][0][k][4 * tn]);
            ulonglong2 b1 = *reinterpret_cast<const ulonglong2*>(&Bs[buf][1][k][4 * tn]);
            ulonglong2 b2 = *reinterpret_cast<const ulonglong2*>(&Bs[buf][2][k][4 * tn]);
            #pragma unroll
            for (int r = 0; r < 4; r++) {
                FMA2(acc[0][r][0], a2[r], b0.x);
                FMA2(acc[0][r][1], a2[r], b0.y);
                FMA2(acc[1][r][0], a2[r], b1.x);
                FMA2(acc[1][r][1], a2[r], b1.y);
                FMA2(acc[2][r][0], a2[r], b2.x);
                FMA2(acc[2][r][1], a2[r], b2.y);
            }
        }
        __syncthreads();
    }

    // Partials: [ks][ch][n*128 + m], coalesced along m
    float* base = g_part + ks * 3 * NGNG;
    #pragma unroll
    for (int c = 0; c < 3; c++) {
        #pragma unroll
        for (int r = 0; r < 4; r++) {
            #pragma unroll
            for (int p = 0; p < 2; p++) {
                unsigned lo, hi;
                UNPACK2(lo, hi, acc[c][r][p]);
                int m = tm + 32 * r;
                int n = tileN + 4 * tn + 2 * p;
                base[c * NGNG + n * NG + m]       = __uint_as_float(lo);
                base[c * NGNG + (n + 1) * NG + m] = __uint_as_float(hi);
            }
        }
    }
}

// ---------------------------------------------------------------------------
// Reduce stage 1: 131072 threads; thread (g, s) sums ~9-10 slices x 3 ch.
// BW-bound instead of latency-bound.
// ---------------------------------------------------------------------------
__global__ void __launch_bounds__(256) reduce1_kernel() {
    int idx = blockIdx.x * 256 + threadIdx.x;   // 0 .. 131071
    int g = idx & (NGNG - 1);
    int s = idx >> 14;                          // 0..7
    int b0 = (s * KSPLIT) >> 3;
    int b1 = ((s + 1) * KSPLIT) >> 3;

    float s0 = 0.0f, s1 = 0.0f, s2 = 0.0f;
    const float* p = g_part + b0 * 3 * NGNG + g;
    #pragma unroll 5
    for (int ks = b0; ks < b1; ks++, p += 3 * NGNG) {
        s0 += p[0];
        s1 += p[NGNG];
        s2 += p[2 * NGNG];
    }
    g_p2[(0 * NSPLIT2 + s) * NGNG + g] = s0;
    g_p2[(1 * NSPLIT2 + s) * NGNG + g] = s1;
    g_p2[(2 * NSPLIT2 + s) * NGNG + g] = s2;
}

// ---------------------------------------------------------------------------
// Reduce stage 2: 16384 threads; sum 8 splits per channel, normalize, write.
// ---------------------------------------------------------------------------
__global__ void __launch_bounds__(256) reduce2_kernel(float* __restrict__ out) {
    int g = blockIdx.x * 256 + threadIdx.x;     // 0..16383
    float t0 = 0.0f, t1 = 0.0f, t2 = 0.0f;
    #pragma unroll
    for (int s = 0; s < NSPLIT2; s++) {
        t0 += g_p2[(0 * NSPLIT2 + s) * NGNG + g];
        t1 += g_p2[(1 * NSPLIT2 + s) * NGNG + g];
        t2 += g_p2[(2 * NSPLIT2 + s) * NGNG + g];
    }
    float inv = 1.0f / t0;
    out[g]            = t0;
    out[NGNG + g]     = t1 * inv;
    out[2 * NGNG + g] = t2 * inv;
}

extern "C" void kernel_launch(void* const* d_in, const int* in_sizes, int n_in,
                              void* d_out, int out_size) {
    const float* X = (const float*)d_in[0];
    const float* Y = (const float*)d_in[1];
    float* out = (float*)d_out;

    main_kernel<<<2 * KSPLIT, NTHREADS>>>(X, Y);
    reduce1_kernel<<<NSPLIT2 * NGNG / 256, 256>>>();
    reduce2_kernel<<<NGNG / 256, 256>>>(out);
}